// round 17
// baseline (speedup 1.0000x reference)
#include <cuda_runtime.h>
#include <cuda_fp16.h>
#include <mma.h>
#include <cstdint>

using namespace nvcuda;

#define NN    10000
#define EE    320000
#define ET    330000
#define GG    100
#define CHN   250
#define HOUT  125
#define SLOPE 0.2f

#define NT    256
#define MPAD  10112     // 158 * 64
#define KP1   384
#define KP2   256

// ---------------- scratch (zero-initialized at module load) --------------------
__device__ __half g_h1[MPAD * 256];          // h ping
__device__ __half g_h2[MPAD * 256];          // h pong
__device__ float  g_fa[NN * CHN];            // layer-4 agg output fp32 (pool source)
__device__ float4 g_atta[NN];                // att ping: x=es0 y=es1 z=ed0 w=ed1
__device__ float4 g_attb[NN];                // att pong
__device__ int    g_cnt[NN];                 // re-zeroed by scan_kernel
__device__ int    g_off[NN + 1];
__device__ int    g_pos[NN];
__device__ int    g_csr[ET];
__device__ __align__(256) __half g_a1h[MPAD * KP1];
#define WOFF1 (NT * KP1)
#define WTOTAL (NT * KP1 + 3 * NT * KP2)
__device__ __align__(256) __half g_wh[WTOTAL];

// ---------------- helpers ------------------------------------------------------
__device__ __forceinline__ uint32_t smem_u32(const void* p) {
    uint32_t a;
    asm("{ .reg .u64 t; cvta.to.shared.u64 t, %1; cvt.u32.u64 %0, t; }" : "=r"(a) : "l"(p));
    return a;
}
__device__ __forceinline__ void cp_async16(uint32_t dst, const void* src) {
    asm volatile("cp.async.cg.shared.global [%0], [%1], 16;" :: "r"(dst), "l"(src));
}
__device__ __forceinline__ void cp_commit() { asm volatile("cp.async.commit_group;" ::: "memory"); }
__device__ __forceinline__ void cp_wait1()  { asm volatile("cp.async.wait_group 1;" ::: "memory"); }
__device__ __forceinline__ float leaky(float x) { return x > 0.f ? x : SLOPE * x; }

// ---------------- CSR build (side branch) --------------------------------------
__global__ void count_kernel(const int* __restrict__ ei) {
    int i = blockIdx.x * blockDim.x + threadIdx.x;
    if (i >= ET) return;
    int dst = (i < EE) ? ei[EE + i] : (i - EE);
    atomicAdd(&g_cnt[dst], 1);
}
__global__ void scan_kernel() {
    __shared__ int sp[1024];
    int t = threadIdx.x;
    int base = t * 10;
    int loc[10];
    int sum = 0;
#pragma unroll
    for (int i = 0; i < 10; i++) {
        int idx = base + i;
        int v = 0;
        if (idx < NN) { v = g_cnt[idx]; g_cnt[idx] = 0; }
        loc[i] = sum; sum += v;
    }
    sp[t] = sum;
    __syncthreads();
    for (int off = 1; off < 1024; off <<= 1) {
        int v = (t >= off) ? sp[t - off] : 0;
        __syncthreads();
        sp[t] += v;
        __syncthreads();
    }
    int pre = sp[t] - sum;
#pragma unroll
    for (int i = 0; i < 10; i++) {
        int idx = base + i;
        if (idx < NN) { int o = pre + loc[i]; g_off[idx] = o; g_pos[idx] = o; }
    }
    if (t == 1023) g_off[NN] = sp[1023];
}
__global__ void scatter_kernel(const int* __restrict__ ei) {
    int i = blockIdx.x * blockDim.x + threadIdx.x;
    if (i >= ET) return;
    int src, dst;
    if (i < EE) { src = ei[i]; dst = ei[EE + i]; }
    else        { src = i - EE; dst = i - EE; }
    int p = atomicAdd(&g_pos[dst], 1);
    g_csr[p] = src;
}

// ---------------- splits -------------------------------------------------------
__global__ void split_a_kernel(const float* __restrict__ in) {
    int idx = blockIdx.x * blockDim.x + threadIdx.x;
    if (idx >= MPAD * KP1) return;
    int r = idx / KP1, k = idx - r * KP1;
    float v = (r < NN && k < 336) ? in[(size_t)r * 336 + k] : 0.f;
    g_a1h[idx] = __float2half(v);
}
__global__ void split_w_all_kernel(const float* __restrict__ W1, const float* __restrict__ W2,
                                   const float* __restrict__ W3, const float* __restrict__ W4)
{
    int idx = blockIdx.x * blockDim.x + threadIdx.x;
    if (idx >= WTOTAL) return;
    const float* W; int K, Kpad, rem;
    if (idx < NT * KP1) { W = W1; K = 336; Kpad = KP1; rem = idx; }
    else {
        int idx2 = idx - NT * KP1;
        int l = idx2 / (NT * KP2);
        rem = idx2 - l * (NT * KP2);
        W = (l == 0) ? W2 : (l == 1) ? W3 : W4;
        K = 250; Kpad = KP2;
    }
    int n = rem / Kpad, k = rem - n * Kpad;
    float v = (n < CHN && k < K) ? W[(size_t)k * CHN + n] : 0.f;
    g_wh[idx] = __float2half(v);
}

// ================= layer-1 GEMM: 64x256 tile, A global, 3-stage ring ===========
#define ALD   40
#define BLD   40
#define G1_A  (64 * ALD)            // 2560 halves / stage
#define G1_B  (256 * BLD)           // 10240 halves / stage
#define G1_ST (G1_A + G1_B)         // 12800 halves = 25600 B
#define CLD2  264
#define G1_AS (3 * G1_ST * 2)       // 76800
#define G1_SMEM (G1_AS + 2048)

// shared epilogue: Cs(64x264 f32 at smem 0) -> h fp16 + att float4
__device__ __forceinline__ void epilogue_64x256(
    float* Cs, const float* s_as, const float* s_ad,
    int tid, int m0, __half* __restrict__ hout, float4* __restrict__ attout)
{
#pragma unroll
    for (int it = 0; it < 32; it++) {
        int idx = it * 256 + tid;           // 8192 half2 slots
        int r = idx >> 7, c2 = idx & 127;
        int grow = m0 + r;
        if (grow < NN && c2 < 125) {
            float v0 = Cs[r * CLD2 + 2 * c2];
            float v1 = Cs[r * CLD2 + 2 * c2 + 1];
            *(__half2*)(hout + (size_t)grow * 256 + 2 * c2) = __floats2half2_rn(v0, v1);
        }
    }
    if (tid < 128) {
        int r = tid >> 1;
        int hf = tid & 1;
        int ccb = hf * 128;
        float s0 = 0.f, d0 = 0.f, s1 = 0.f, d1 = 0.f;
#pragma unroll 8
        for (int q = 0; q < 128; q++) {
            int cc = ccb + q;
            float v = Cs[r * CLD2 + cc];
            float a = s_as[cc], bv = s_ad[cc];
            if (cc < HOUT) { s0 += v * a; d0 += v * bv; }
            else           { s1 += v * a; d1 += v * bv; }
        }
        s0 += __shfl_xor_sync(0xffffffffu, s0, 1);
        d0 += __shfl_xor_sync(0xffffffffu, d0, 1);
        s1 += __shfl_xor_sync(0xffffffffu, s1, 1);
        d1 += __shfl_xor_sync(0xffffffffu, d1, 1);
        int grow = m0 + r;
        if (hf == 0 && grow < NN)
            attout[grow] = make_float4(s0, s1, d0, d1);
    }
}

__global__ __launch_bounds__(256, 2) void gemm1_kernel(
    const __half* __restrict__ Ain, const __half* __restrict__ Bin,
    const float* __restrict__ asrc, const float* __restrict__ adst,
    __half* __restrict__ hout, float4* __restrict__ attout)
{
    extern __shared__ char smem[];
    float* Cs = (float*)smem;
    float* s_as = (float*)(smem + G1_AS);
    float* s_ad = (float*)(smem + G1_AS + 1024);

    int tid = threadIdx.x;
    int wid = tid >> 5, wm = wid >> 2, wn = wid & 3;
    int m0 = blockIdx.x * 64;
    uint32_t sbase = smem_u32(smem);

    s_as[tid] = (tid < CHN) ? asrc[tid] : 0.f;
    s_ad[tid] = (tid < CHN) ? adst[tid] : 0.f;

    const int niter = KP1 >> 5;   // 12
    auto load_stage = [&](int st, int kb) {
        int kk = kb << 5;
        uint32_t stb = sbase + st * G1_ST * 2;
        {
            int rowa = tid >> 2, grpa = tid & 3;
            cp_async16(stb + (rowa * ALD + grpa * 8) * 2,
                       Ain + (size_t)(m0 + rowa) * KP1 + kk + grpa * 8);
        }
        // B: 256 rows x 32 halves = 1024 x 16B chunks -> 4 per thread
#pragma unroll
        for (int i = 0; i < 4; i++) {
            int c = tid + i * 256;
            int rowb = c >> 2, grpb = c & 3;
            cp_async16(stb + (G1_A + rowb * BLD + grpb * 8) * 2,
                       Bin + (size_t)rowb * KP1 + kk + grpb * 8);
        }
        cp_commit();
    };

    wmma::fragment<wmma::accumulator, 16, 16, 16, float> c[2][4];
#pragma unroll
    for (int i = 0; i < 2; i++)
#pragma unroll
        for (int j = 0; j < 4; j++) wmma::fill_fragment(c[i][j], 0.f);

    load_stage(0, 0);
    load_stage(1, 1);
    int slot = 0;
    for (int kb = 0; kb < niter; kb++) {
        cp_wait1();
        __syncthreads();
        int nslot = slot + 2; if (nslot >= 3) nslot -= 3;
        if (kb + 2 < niter) load_stage(nslot, kb + 2);
        else                cp_commit();

        const __half* stg = (const __half*)(smem + (size_t)slot * G1_ST * 2);
        const __half* at = stg + wm * 32 * ALD;
        const __half* bt = stg + G1_A + wn * 64 * BLD;
#pragma unroll
        for (int ks = 0; ks < 2; ks++) {
            wmma::fragment<wmma::matrix_a, 16, 16, 16, __half, wmma::row_major> a0, a1;
            wmma::load_matrix_sync(a0, at + ks * 16, ALD);
            wmma::load_matrix_sync(a1, at + 16 * ALD + ks * 16, ALD);
#pragma unroll
            for (int j = 0; j < 4; j++) {
                wmma::fragment<wmma::matrix_b, 16, 16, 16, __half, wmma::col_major> b;
                wmma::load_matrix_sync(b, bt + j * 16 * BLD + ks * 16, BLD);
                wmma::mma_sync(c[0][j], a0, b, c[0][j]);
                wmma::mma_sync(c[1][j], a1, b, c[1][j]);
            }
        }
        slot = (slot + 1 == 3) ? 0 : slot + 1;
    }
    __syncthreads();
#pragma unroll
    for (int i = 0; i < 2; i++)
#pragma unroll
        for (int j = 0; j < 4; j++)
            wmma::store_matrix_sync(Cs + (wm * 32 + i * 16) * CLD2 + wn * 64 + j * 16,
                                    c[i][j], CLD2, wmma::mem_row_major);
    __syncthreads();
    epilogue_64x256(Cs, s_as, s_ad, tid, m0, hout, attout);
}

// ====== fused agg(layer l) + GEMM(layer l+1): 64 rows, warp-per-node agg ======
#define FALD  264
#define F_A_BYTES (64 * FALD * 2)          // 33792
#define F_B_OFF   F_A_BYTES
#define FB_STG    (256 * BLD)              // 10240 halves = 20480 B
#define F_AS_OFF  (F_B_OFF + 3 * FB_STG * 2)   // 95232
#define F_AD_OFF  (F_AS_OFF + 1024)
#define F_SRC_OFF (F_AD_OFF + 1024)        // 97280
#define F_P0_OFF  (F_SRC_OFF + 4096)
#define F_P1_OFF  (F_P0_OFF + 4096)
#define F_SMEM    (F_P1_OFF + 4096)        // 109568

__global__ __launch_bounds__(256, 2) void fused_agg_gemm_kernel(
    const __half* __restrict__ h_in, const float4* __restrict__ att_in,
    const float* __restrict__ bias,
    const __half* __restrict__ Bin,
    const float* __restrict__ asrc, const float* __restrict__ adst,
    __half* __restrict__ h_out, float4* __restrict__ att_out)
{
    extern __shared__ char smem[];
    __half* As = (__half*)smem;
    float* Cs = (float*)smem;
    float* s_as = (float*)(smem + F_AS_OFF);
    float* s_ad = (float*)(smem + F_AD_OFF);

    int tid = threadIdx.x;
    int wid = tid >> 5, lane = tid & 31;
    int m0 = blockIdx.x * 64;
    uint32_t sbase = smem_u32(smem);

    auto load_b = [&](int st, int kb) {
        int kk = kb << 5;
        uint32_t stb = sbase + F_B_OFF + st * FB_STG * 2;
        // B: 256 rows x 32 halves = 1024 chunks -> 4 per thread
#pragma unroll
        for (int i = 0; i < 4; i++) {
            int c = tid + i * 256;
            int rowb = c >> 2, grp = c & 3;
            cp_async16(stb + (rowb * BLD + grp * 8) * 2,
                       Bin + (size_t)rowb * KP2 + kk + grp * 8);
        }
        cp_commit();
    };
    // prefetch B stages 0,1 — land while phase A runs
    load_b(0, 0);
    load_b(1, 1);

    s_as[tid] = (tid < CHN) ? asrc[tid] : 0.f;
    s_ad[tid] = (tid < CHN) ? adst[tid] : 0.f;

    // ---------- phase A: aggregation, one warp per node, 8 nodes each ----------
    int*   ssrc = (int*)(smem + F_SRC_OFF) + wid * 128;
    float* sp0  = (float*)(smem + F_P0_OFF) + wid * 128;
    float* sp1  = (float*)(smem + F_P1_OFF) + wid * 128;

    for (int t = 0; t < 8; t++) {
        int r = wid * 8 + t;
        int i = m0 + r;
        float acc[4][2] = {{0.f,0.f},{0.f,0.f},{0.f,0.f},{0.f,0.f}};
        if (i < NN) {
            int s = g_off[i], e = g_off[i + 1], d = e - s;
            float4 ai = att_in[i];
            float ed0 = ai.z, ed1 = ai.w;

            if (d <= 128) {
                float m0f = -1e30f, m1f = -1e30f;
                for (int j = lane; j < d; j += 32) {
                    int src = g_csr[s + j];
                    float4 b = att_in[src];
                    float l0 = leaky(b.x + ed0), l1 = leaky(b.y + ed1);
                    ssrc[j] = src; sp0[j] = l0; sp1[j] = l1;
                    m0f = fmaxf(m0f, l0); m1f = fmaxf(m1f, l1);
                }
#pragma unroll
                for (int o = 16; o; o >>= 1) {
                    m0f = fmaxf(m0f, __shfl_xor_sync(0xffffffffu, m0f, o));
                    m1f = fmaxf(m1f, __shfl_xor_sync(0xffffffffu, m1f, o));
                }
                __syncwarp();
                float sm0 = 0.f, sm1 = 0.f;
                for (int j = lane; j < d; j += 32) {
                    float p0 = __expf(sp0[j] - m0f);
                    float p1 = __expf(sp1[j] - m1f);
                    sp0[j] = p0; sp1[j] = p1;
                    sm0 += p0; sm1 += p1;
                }
#pragma unroll
                for (int o = 16; o; o >>= 1) {
                    sm0 += __shfl_xor_sync(0xffffffffu, sm0, o);
                    sm1 += __shfl_xor_sync(0xffffffffu, sm1, o);
                }
                float r0 = 1.f / (sm0 + 1e-16f), r1 = 1.f / (sm1 + 1e-16f);
                __syncwarp();
                for (int k = 0; k < d; k++) {
                    int sk = ssrc[k];
                    float a0 = sp0[k] * r0, a1 = sp1[k] * r1;
                    const __half2* hr = (const __half2*)(h_in + (size_t)sk * 256);
#pragma unroll
                    for (int q = 0; q < 4; q++) {
                        int cc = lane + 32 * q;
                        if (cc < 125) {
                            float2 f = __half22float2(hr[cc]);
                            float aa = (2 * cc < HOUT) ? a0 : a1;
                            float ab = (2 * cc + 1 < HOUT) ? a0 : a1;
                            acc[q][0] += aa * f.x;
                            acc[q][1] += ab * f.y;
                        }
                    }
                }
                __syncwarp();
            } else {
                float m0f = -1e30f, m1f = -1e30f;
                for (int j = lane; j < d; j += 32) {
                    int src = g_csr[s + j];
                    float4 b = att_in[src];
                    m0f = fmaxf(m0f, leaky(b.x + ed0));
                    m1f = fmaxf(m1f, leaky(b.y + ed1));
                }
#pragma unroll
                for (int o = 16; o; o >>= 1) {
                    m0f = fmaxf(m0f, __shfl_xor_sync(0xffffffffu, m0f, o));
                    m1f = fmaxf(m1f, __shfl_xor_sync(0xffffffffu, m1f, o));
                }
                float sm0 = 0.f, sm1 = 0.f;
                for (int j = lane; j < d; j += 32) {
                    int src = g_csr[s + j];
                    float4 b = att_in[src];
                    sm0 += __expf(leaky(b.x + ed0) - m0f);
                    sm1 += __expf(leaky(b.y + ed1) - m1f);
                }
#pragma unroll
                for (int o = 16; o; o >>= 1) {
                    sm0 += __shfl_xor_sync(0xffffffffu, sm0, o);
                    sm1 += __shfl_xor_sync(0xffffffffu, sm1, o);
                }
                float r0 = 1.f / (sm0 + 1e-16f), r1 = 1.f / (sm1 + 1e-16f);
                for (int cs = 0; cs < d; cs += 128) {
                    int cnt = min(128, d - cs);
                    for (int j = lane; j < cnt; j += 32) {
                        int src = g_csr[s + cs + j];
                        float4 b = att_in[src];
                        ssrc[j] = src;
                        sp0[j] = __expf(leaky(b.x + ed0) - m0f) * r0;
                        sp1[j] = __expf(leaky(b.y + ed1) - m1f) * r1;
                    }
                    __syncwarp();
                    for (int k = 0; k < cnt; k++) {
                        int sk = ssrc[k];
                        float a0 = sp0[k], a1 = sp1[k];
                        const __half2* hr = (const __half2*)(h_in + (size_t)sk * 256);
#pragma unroll
                        for (int q = 0; q < 4; q++) {
                            int cc = lane + 32 * q;
                            if (cc < 125) {
                                float2 f = __half22float2(hr[cc]);
                                float aa = (2 * cc < HOUT) ? a0 : a1;
                                float ab = (2 * cc + 1 < HOUT) ? a0 : a1;
                                acc[q][0] += aa * f.x;
                                acc[q][1] += ab * f.y;
                            }
                        }
                    }
                    __syncwarp();
                }
            }
        }
        // write A row r: relu(acc + bias), fp16; zero pad columns
        __half2* arow = (__half2*)(As + r * FALD);
#pragma unroll
        for (int q = 0; q < 4; q++) {
            int cc = lane + 32 * q;
            float v0 = 0.f, v1 = 0.f;
            if (i < NN && 2 * cc < CHN) {
                v0 = fmaxf(acc[q][0] + bias[2 * cc], 0.f);
                v1 = fmaxf(acc[q][1] + bias[2 * cc + 1], 0.f);
            }
            arow[cc] = __floats2half2_rn(v0, v1);
        }
    }
    __syncthreads();

    // ---------- phase B: GEMM, A in smem, B 3-stage ring ----------
    int wm = wid >> 2, wn = wid & 3;
    wmma::fragment<wmma::accumulator, 16, 16, 16, float> c[2][4];
#pragma unroll
    for (int i = 0; i < 2; i++)
#pragma unroll
        for (int j = 0; j < 4; j++) wmma::fill_fragment(c[i][j], 0.f);

    const int niter = KP2 >> 5;   // 8
    int slot = 0;
    for (int kb = 0; kb < niter; kb++) {
        cp_wait1();
        __syncthreads();
        int nslot = slot + 2; if (nslot >= 3) nslot -= 3;
        if (kb + 2 < niter) load_b(nslot, kb + 2);
        else                cp_commit();

        const __half* bt = (const __half*)(smem + F_B_OFF + (size_t)slot * FB_STG * 2)
                           + wn * 64 * BLD;
        const __half* at = As + wm * 32 * FALD + kb * 32;
#pragma unroll
        for (int ks = 0; ks < 2; ks++) {
            wmma::fragment<wmma::matrix_a, 16, 16, 16, __half, wmma::row_major> a0, a1;
            wmma::load_matrix_sync(a0, at + ks * 16, FALD);
            wmma::load_matrix_sync(a1, at + 16 * FALD + ks * 16, FALD);
#pragma unroll
            for (int j = 0; j < 4; j++) {
                wmma::fragment<wmma::matrix_b, 16, 16, 16, __half, wmma::col_major> b;
                wmma::load_matrix_sync(b, bt + j * 16 * BLD + ks * 16, BLD);
                wmma::mma_sync(c[0][j], a0, b, c[0][j]);
                wmma::mma_sync(c[1][j], a1, b, c[1][j]);
            }
        }
        slot = (slot + 1 == 3) ? 0 : slot + 1;
    }
    __syncthreads();
#pragma unroll
    for (int i = 0; i < 2; i++)
#pragma unroll
        for (int j = 0; j < 4; j++)
            wmma::store_matrix_sync(Cs + (wm * 32 + i * 16) * CLD2 + wn * 64 + j * 16,
                                    c[i][j], CLD2, wmma::mem_row_major);
    __syncthreads();
    epilogue_64x256(Cs, s_as, s_ad, tid, m0, h_out, att_out);
}

// ---------------- final aggregation (layer 4, fp32 out) -------------------------
__global__ __launch_bounds__(128) void agg4_kernel(const float* __restrict__ bias,
                                                   const __half* __restrict__ h_in,
                                                   const float4* __restrict__ att,
                                                   float* __restrict__ of32)
{
    int i = blockIdx.x;
    int tid = threadIdx.x;
    int lane = tid & 31, warp = tid >> 5;

    __shared__ float w0[4], w1[4];
    __shared__ int   s_src[128];
    __shared__ float s_a0[128], s_a1[128];

    int s = g_off[i], e = g_off[i + 1];
    int d = e - s;
    float4 ai = att[i];
    float ed0 = ai.z, ed1 = ai.w;

    float acc0 = 0.f, acc1 = 0.f;
    int c0 = 2 * tid;
    bool act = (tid < HOUT);
    bool head0a = (c0 < HOUT);
    bool head0b = (c0 + 1 < HOUT);

    if (d <= 128) {
        bool valid = tid < d;
        int src = 0;
        float l0 = -1e30f, l1 = -1e30f;
        if (valid) {
            src = g_csr[s + tid];
            float4 b = att[src];
            l0 = leaky(b.x + ed0);
            l1 = leaky(b.y + ed1);
        }
        float m0 = l0, m1 = l1;
#pragma unroll
        for (int o = 16; o; o >>= 1) {
            m0 = fmaxf(m0, __shfl_xor_sync(0xffffffffu, m0, o));
            m1 = fmaxf(m1, __shfl_xor_sync(0xffffffffu, m1, o));
        }
        if (lane == 0) { w0[warp] = m0; w1[warp] = m1; }
        __syncthreads();
        m0 = fmaxf(fmaxf(w0[0], w0[1]), fmaxf(w0[2], w0[3]));
        m1 = fmaxf(fmaxf(w1[0], w1[1]), fmaxf(w1[2], w1[3]));
        __syncthreads();

        float p0 = valid ? __expf(l0 - m0) : 0.f;
        float p1 = valid ? __expf(l1 - m1) : 0.f;
        float d0 = p0, d1 = p1;
#pragma unroll
        for (int o = 16; o; o >>= 1) {
            d0 += __shfl_xor_sync(0xffffffffu, d0, o);
            d1 += __shfl_xor_sync(0xffffffffu, d1, o);
        }
        if (lane == 0) { w0[warp] = d0; w1[warp] = d1; }
        __syncthreads();
        d0 = w0[0] + w0[1] + w0[2] + w0[3] + 1e-16f;
        d1 = w1[0] + w1[1] + w1[2] + w1[3] + 1e-16f;
        float r0 = 1.0f / d0, r1 = 1.0f / d1;

        s_src[tid] = src;
        s_a0[tid] = p0 * r0;
        s_a1[tid] = p1 * r1;
        __syncthreads();

        if (act) {
#pragma unroll 4
            for (int k = 0; k < d; k++) {
                int sk = s_src[k];
                float2 hv = __half22float2(*(const __half2*)(h_in + (size_t)sk * 256 + c0));
                float aa = head0a ? s_a0[k] : s_a1[k];
                float ab = head0b ? s_a0[k] : s_a1[k];
                acc0 += aa * hv.x;
                acc1 += ab * hv.y;
            }
        }
    } else {
        float m0 = -1e30f, m1 = -1e30f;
        for (int j = s + tid; j < e; j += 128) {
            float4 b = att[g_csr[j]];
            m0 = fmaxf(m0, leaky(b.x + ed0));
            m1 = fmaxf(m1, leaky(b.y + ed1));
        }
#pragma unroll
        for (int o = 16; o; o >>= 1) {
            m0 = fmaxf(m0, __shfl_xor_sync(0xffffffffu, m0, o));
            m1 = fmaxf(m1, __shfl_xor_sync(0xffffffffu, m1, o));
        }
        if (lane == 0) { w0[warp] = m0; w1[warp] = m1; }
        __syncthreads();
        m0 = fmaxf(fmaxf(w0[0], w0[1]), fmaxf(w0[2], w0[3]));
        m1 = fmaxf(fmaxf(w1[0], w1[1]), fmaxf(w1[2], w1[3]));
        __syncthreads();

        float d0 = 0.f, d1 = 0.f;
        for (int j = s + tid; j < e; j += 128) {
            float4 b = att[g_csr[j]];
            d0 += __expf(leaky(b.x + ed0) - m0);
            d1 += __expf(leaky(b.y + ed1) - m1);
        }
#pragma unroll
        for (int o = 16; o; o >>= 1) {
            d0 += __shfl_xor_sync(0xffffffffu, d0, o);
            d1 += __shfl_xor_sync(0xffffffffu, d1, o);
        }
        if (lane == 0) { w0[warp] = d0; w1[warp] = d1; }
        __syncthreads();
        d0 = w0[0] + w0[1] + w0[2] + w0[3] + 1e-16f;
        d1 = w1[0] + w1[1] + w1[2] + w1[3] + 1e-16f;
        float r0 = 1.0f / d0, r1 = 1.0f / d1;

        for (int base = s; base < e; base += 128) {
            int j = base + tid;
            if (j < e) {
                int src = g_csr[j];
                float4 b = att[src];
                s_src[tid] = src;
                s_a0[tid] = __expf(leaky(b.x + ed0) - m0) * r0;
                s_a1[tid] = __expf(leaky(b.y + ed1) - m1) * r1;
            }
            __syncthreads();
            int cnt = min(128, e - base);
            if (act) {
#pragma unroll 4
                for (int k = 0; k < cnt; k++) {
                    int sk = s_src[k];
                    float2 hv = __half22float2(*(const __half2*)(h_in + (size_t)sk * 256 + c0));
                    float aa = head0a ? s_a0[k] : s_a1[k];
                    float ab = head0b ? s_a0[k] : s_a1[k];
                    acc0 += aa * hv.x;
                    acc1 += ab * hv.y;
                }
            }
            __syncthreads();
        }
    }

    if (act) {
        of32[(size_t)i * CHN + c0]     = fmaxf(acc0 + bias[c0], 0.f);
        of32[(size_t)i * CHN + c0 + 1] = fmaxf(acc1 + bias[c0 + 1], 0.f);
    }
}

// ---------------- fused pool + 4-layer MLP (one block per graph) ---------------
__global__ __launch_bounds__(256) void pool_mlp_kernel(
    const int* __restrict__ batch, const float* __restrict__ feat,
    const float* __restrict__ lw1, const float* __restrict__ lb1,
    const float* __restrict__ lw2, const float* __restrict__ lb2,
    const float* __restrict__ lw3, const float* __restrict__ lb3,
    const float* __restrict__ lw4, const float* __restrict__ lb4,
    float* __restrict__ out)
{
    int g = blockIdx.x;
    int tid = threadIdx.x;
    __shared__ int ss, se;
    __shared__ float sg[CHN], t1[200], t2[100], t3[100];

    if (tid == 0) {
        int lo = 0, hi = NN;
        while (lo < hi) { int mid = (lo + hi) >> 1; if (batch[mid] < g) lo = mid + 1; else hi = mid; }
        ss = lo;
        lo = 0; hi = NN;
        while (lo < hi) { int mid = (lo + hi) >> 1; if (batch[mid] < g + 1) lo = mid + 1; else hi = mid; }
        se = lo;
    }
    __syncthreads();
    if (tid < CHN) {
        float sum = 0.f;
        for (int i = ss; i < se; i++) sum += feat[(size_t)i * CHN + tid];
        sg[tid] = sum / fmaxf((float)(se - ss), 1.0f);
    }
    __syncthreads();
    if (tid < 200) {
        float s = lb1[tid];
        for (int k = 0; k < 250; k++) s += sg[k] * lw1[k * 200 + tid];
        t1[tid] = fmaxf(s, 0.f);
    }
    __syncthreads();
    if (tid < 100) {
        float s = lb2[tid];
        for (int k = 0; k < 200; k++) s += t1[k] * lw2[k * 100 + tid];
        t2[tid] = fmaxf(s, 0.f);
    }
    __syncthreads();
    if (tid < 100) {
        float s = lb3[tid];
        for (int k = 0; k < 100; k++) s += t2[k] * lw3[k * 100 + tid];
        t3[tid] = fmaxf(s, 0.f);
    }
    __syncthreads();
    if (tid < 29) {
        float s = lb4[tid];
        for (int k = 0; k < 100; k++) s += t3[k] * lw4[k * 29 + tid];
        out[g * 29 + tid] = s;
    }
}

// ---------------- driver --------------------------------------------------------
extern "C" void kernel_launch(void* const* d_in, const int* in_sizes, int n_in,
                              void* d_out, int out_size)
{
    const float* x     = (const float*)d_in[0];
    const int*   ei    = (const int*)d_in[1];
    const int*   batch = (const int*)d_in[2];
    const float* W[4]    = {(const float*)d_in[3],  (const float*)d_in[7],
                            (const float*)d_in[11], (const float*)d_in[15]};
    const float* Asrc[4] = {(const float*)d_in[4],  (const float*)d_in[8],
                            (const float*)d_in[12], (const float*)d_in[16]};
    const float* Adst[4] = {(const float*)d_in[5],  (const float*)d_in[9],
                            (const float*)d_in[13], (const float*)d_in[17]};
    const float* Bb[4]   = {(const float*)d_in[6],  (const float*)d_in[10],
                            (const float*)d_in[14], (const float*)d_in[18]};
    const float* lw1 = (const float*)d_in[19]; const float* lb1 = (const float*)d_in[20];
    const float* lw2 = (const float*)d_in[21]; const float* lb2 = (const float*)d_in[22];
    const float* lw3 = (const float*)d_in[23]; const float* lb3 = (const float*)d_in[24];
    const float* lw4 = (const float*)d_in[25]; const float* lb4 = (const float*)d_in[26];
    float* out = (float*)d_out;

    float *faP;
    __half *h1P, *h2P, *a1hP, *whP;
    float4 *attaP, *attbP;
    cudaGetSymbolAddress((void**)&h1P,  g_h1);
    cudaGetSymbolAddress((void**)&h2P,  g_h2);
    cudaGetSymbolAddress((void**)&faP,  g_fa);
    cudaGetSymbolAddress((void**)&a1hP, g_a1h);
    cudaGetSymbolAddress((void**)&whP,  g_wh);
    cudaGetSymbolAddress((void**)&attaP, g_atta);
    cudaGetSymbolAddress((void**)&attbP, g_attb);

    cudaFuncSetAttribute(gemm1_kernel,
                         cudaFuncAttributeMaxDynamicSharedMemorySize, G1_SMEM);
    cudaFuncSetAttribute(fused_agg_gemm_kernel,
                         cudaFuncAttributeMaxDynamicSharedMemorySize, F_SMEM);

    // ---- fork: side stream does split_w then CSR build ----
    cudaStream_t s2;
    cudaStreamCreateWithFlags(&s2, cudaStreamNonBlocking);
    cudaEvent_t evFork, evW, evJoin;
    cudaEventCreateWithFlags(&evFork, cudaEventDisableTiming);
    cudaEventCreateWithFlags(&evW, cudaEventDisableTiming);
    cudaEventCreateWithFlags(&evJoin, cudaEventDisableTiming);

    cudaEventRecord(evFork, 0);
    cudaStreamWaitEvent(s2, evFork, 0);
    split_w_all_kernel<<<(WTOTAL + 255) / 256, 256, 0, s2>>>(W[0], W[1], W[2], W[3]);
    cudaEventRecord(evW, s2);
    count_kernel<<<(ET + 255) / 256, 256, 0, s2>>>(ei);
    scan_kernel<<<1, 1024, 0, s2>>>();
    scatter_kernel<<<(ET + 255) / 256, 256, 0, s2>>>(ei);
    cudaEventRecord(evJoin, s2);

    // main: split_a, then layer-1 GEMM (needs weights)
    split_a_kernel<<<(MPAD * KP1 + 255) / 256, 256>>>(x);
    cudaStreamWaitEvent(0, evW, 0);
    int nblk = MPAD / 64;   // 158
    gemm1_kernel<<<nblk, 256, G1_SMEM>>>(a1hP, whP, Asrc[0], Adst[0], h1P, attaP);

    // join CSR before first fused layer
    cudaStreamWaitEvent(0, evJoin, 0);
    fused_agg_gemm_kernel<<<nblk, 256, F_SMEM>>>(
        h1P, attaP, Bb[0], whP + WOFF1, Asrc[1], Adst[1], h2P, attbP);
    fused_agg_gemm_kernel<<<nblk, 256, F_SMEM>>>(
        h2P, attbP, Bb[1], whP + WOFF1 + (size_t)NT * KP2, Asrc[2], Adst[2], h1P, attaP);
    fused_agg_gemm_kernel<<<nblk, 256, F_SMEM>>>(
        h1P, attaP, Bb[2], whP + WOFF1 + 2 * (size_t)NT * KP2, Asrc[3], Adst[3], h2P, attbP);

    agg4_kernel<<<NN, 128>>>(Bb[3], h2P, attbP, faP);

    pool_mlp_kernel<<<GG, 256>>>(batch, faP, lw1, lb1, lw2, lb2, lw3, lb3, lw4, lb4, out);
}